// round 9
// baseline (speedup 1.0000x reference)
#include <cuda_runtime.h>
#include <cfloat>

// xp: (32, 64, 64, 512) fp32, m innermost. out: (32, 48*512), bin = iw*6+ih.
// Resize is identity. Row bins: 8 rows each. Col edges: {0,11,21,32,43,53,64}.
//
// R9: R3's best kernel (42.6us ncu, 78.2% DRAM = chip LTS cap) + straggler
// shaping: 1D grid reordered so the 512 NARROW bins (nc=10, ih in {1,4})
// launch LAST. The final drain wave (~352 blocks at 8 blocks/SM residency)
// is then composed entirely of 10-column blocks (~9% less work each),
// shortening the undersaturated tail. nc also becomes compile-time per
// branch (no has11 predicate). Inner loop unchanged from R3: 2-row
// interleave x fully-unrolled columns, __ldcs.

#define B_DIM 32
#define W_DIM 64
#define H_DIM 64
#define M_DIM 512
#define W_BINS 8
#define H_BINS 6
#define M4 (M_DIM / 4)            // 128 float4 lanes per (b,r,c)
#define ROW_STRIDE (H_DIM * M4)   // float4 elems per image row
#define N_WIDE (B_DIM * W_BINS * 4)   // 1024 blocks with nc=11 (ih 0,2,3,5)

__constant__ int IH_WIDE[4]   = {0, 2, 3, 5};   // c1: 0,21,32,53  (width 11)
__constant__ int IH_NARROW[2] = {1, 4};         // c1: 11,43       (width 10)
__constant__ int C_EDGE[H_BINS + 1] = {0, 11, 21, 32, 43, 53, 64};

static __device__ __forceinline__ float4 fmax4(float4 a, float4 b) {
    a.x = fmaxf(a.x, b.x);
    a.y = fmaxf(a.y, b.y);
    a.z = fmaxf(a.z, b.z);
    a.w = fmaxf(a.w, b.w);
    return a;
}

template <int NC>
static __device__ __forceinline__ float4
reduce_bin(const float4* __restrict__ base) {
    float4 acc = make_float4(-FLT_MAX, -FLT_MAX, -FLT_MAX, -FLT_MAX);
    // 8 rows as 4 row-pairs; per pair 2*NC independent 16B loads in flight.
    #pragma unroll 1
    for (int rp = 0; rp < 4; ++rp) {
        const float4* r0 = base + (size_t)(2 * rp) * ROW_STRIDE;
        const float4* r1 = r0 + ROW_STRIDE;
        #pragma unroll
        for (int c = 0; c < NC; ++c) {
            float4 va = __ldcs(r0 + (size_t)c * M4);
            float4 vb = __ldcs(r1 + (size_t)c * M4);
            acc = fmax4(acc, fmax4(va, vb));
        }
    }
    return acc;
}

// 1D grid, 1536 blocks. fid < 1024: wide bins (nc=11). fid >= 1024: narrow
// (nc=10), launched last so the drain wave is all-narrow. Within each group,
// ih varies fastest, then iw, then b (spreads addresses across L2).
__global__ __launch_bounds__(M4, 8)
void adaptive_maxpool_kernel(const float4* __restrict__ x4,
                             float4* __restrict__ out4) {
    const int fid = blockIdx.x;
    const int t = threadIdx.x;        // 0..127

    int b, iw, ih;
    bool wide;
    if (fid < N_WIDE) {
        wide = true;
        ih = IH_WIDE[fid & 3];
        const int rest = fid >> 2;    // 0..255
        iw = rest & 7;
        b  = rest >> 3;
    } else {
        wide = false;
        const int v = fid - N_WIDE;   // 0..511
        ih = IH_NARROW[v & 1];
        const int rest = v >> 1;      // 0..255
        iw = rest & 7;
        b  = rest >> 3;
    }

    const int r1 = iw * (W_DIM / W_BINS);   // 8 rows per bin
    const int c1 = C_EDGE[ih];

    const float4* base =
        x4 + ((size_t)(b * W_DIM + r1) * H_DIM + c1) * M4 + t;

    float4 acc = wide ? reduce_bin<11>(base) : reduce_bin<10>(base);

    const int bin = iw * H_BINS + ih;
    out4[((size_t)b * (W_BINS * H_BINS) + bin) * M4 + t] = acc;
}

extern "C" void kernel_launch(void* const* d_in, const int* in_sizes, int n_in,
                              void* d_out, int out_size) {
    (void)in_sizes; (void)n_in; (void)out_size;
    const float4* x4 = (const float4*)d_in[0];
    float4* o4 = (float4*)d_out;

    adaptive_maxpool_kernel<<<W_BINS * H_BINS * B_DIM, M4>>>(x4, o4);
}

// round 10
// speedup vs baseline: 1.0651x; 1.0651x over previous
#include <cuda_runtime.h>
#include <cfloat>

// xp: (32, 64, 64, 512) fp32, m innermost. out: (32, 48*512), bin = iw*6+ih.
// Resize is identity. Row bins: 8 rows each. Col edges: {0,11,21,32,43,53,64}.
//
// R10 (FINAL): byte-identical revert to R3, the measured optimum of this
// session. Evidence across R1-R9: the workload pins at the chip's
// path-independent LTS/DRAM cap (~6.39 TB/s, 78% of spec) for any kernel
// with warp-MLP >= ~8; occupancy (24-87%), access pattern (22KB slivers vs
// 1MB linear), datapath (LDG vs TMA bulk), cache hints, block size, and
// launch order are all neutral-or-worse. R3 = (b,bin) 2D grid, 128 threads,
// 2-row interleave x fully-unrolled 10/11 columns (~20 independent
// LDG.E.128 per thread), __ldcs, launch_bounds(128,6). 42.6us ncu = 98.6%
// of the 42.0us achieved-bandwidth floor.

#define B_DIM 32
#define W_DIM 64
#define H_DIM 64
#define M_DIM 512
#define W_BINS 8
#define H_BINS 6
#define M4 (M_DIM / 4)            // 128 float4 lanes per (b,r,c)
#define ROW_STRIDE (H_DIM * M4)   // float4 elems per image row

__constant__ int C_EDGE[H_BINS + 1] = {0, 11, 21, 32, 43, 53, 64};

static __device__ __forceinline__ float4 fmax4(float4 a, float4 b) {
    a.x = fmaxf(a.x, b.x);
    a.y = fmaxf(a.y, b.y);
    a.z = fmaxf(a.z, b.z);
    a.w = fmaxf(a.w, b.w);
    return a;
}

static __device__ __forceinline__ float4 ldcs4(const float4* p) {
    return __ldcs(p);
}

// One block per (batch, bin). 128 threads; thread t owns channels [4t, 4t+4).
__global__ __launch_bounds__(M4, 6)
void adaptive_maxpool_kernel(const float4* __restrict__ x4, float4* __restrict__ out4) {
    const int bin = blockIdx.x;       // 0..47  (iw*6 + ih)
    const int b   = blockIdx.y;       // 0..31
    const int iw  = bin / H_BINS;
    const int ih  = bin - iw * H_BINS;

    const int r1 = iw * (W_DIM / W_BINS);          // 8 rows per bin
    const int c1 = C_EDGE[ih];
    const bool has11 = (C_EDGE[ih + 1] - c1) == 11; // widths are 10 or 11

    const int t = threadIdx.x;                     // 0..127
    const float4* base =
        x4 + ((size_t)(b * W_DIM + r1) * H_DIM + c1) * M4 + t;

    float4 acc = make_float4(-FLT_MAX, -FLT_MAX, -FLT_MAX, -FLT_MAX);

    // 8 rows as 4 row-pairs; per pair issue 2x10 (+2) independent loads.
    #pragma unroll 1
    for (int rp = 0; rp < 4; ++rp) {
        const float4* r0 = base + (size_t)(2 * rp) * ROW_STRIDE;
        const float4* r1p = r0 + ROW_STRIDE;

        #pragma unroll
        for (int c = 0; c < 10; ++c) {
            float4 va = ldcs4(r0  + (size_t)c * M4);
            float4 vb = ldcs4(r1p + (size_t)c * M4);
            acc = fmax4(acc, fmax4(va, vb));
        }
        if (has11) {
            float4 va = ldcs4(r0  + (size_t)10 * M4);
            float4 vb = ldcs4(r1p + (size_t)10 * M4);
            acc = fmax4(acc, fmax4(va, vb));
        }
    }

    out4[((size_t)b * (W_BINS * H_BINS) + bin) * M4 + t] = acc;
}

extern "C" void kernel_launch(void* const* d_in, const int* in_sizes, int n_in,
                              void* d_out, int out_size) {
    (void)in_sizes; (void)n_in; (void)out_size;
    const float4* x4 = (const float4*)d_in[0];
    float4* o4 = (float4*)d_out;

    dim3 grid(W_BINS * H_BINS, B_DIM);   // (48, 32) = 1536 blocks
    adaptive_maxpool_kernel<<<grid, M4>>>(x4, o4);
}